// round 4
// baseline (speedup 1.0000x reference)
#include <cuda_runtime.h>
#include <cuda_fp16.h>
#include <cstdint>

#define T_STEPS 100
#define N_IN    784
#define N_HID   100
#define N_OUT   10
#define BATCH   2048
#define M_TOTAL (BATCH * T_STEPS)   // 204800
#define NPB     112                 // N padded to 14 * 8
#define NK      49                  // 784 / 16 k-chunks
#define M_CTA   256

// smem layout (per stage), 48-byte row pitch => conflict-free ldmatrix
#define SA        48
#define A_HI_OFF  0
#define A_LO_OFF  (M_CTA * SA)                // 12288
#define B_HI_OFF  (2 * M_CTA * SA)            // 24576
#define B_LO_OFF  (B_HI_OFF + NPB * SA)       // 29952
#define STAGE     (B_LO_OFF + NPB * SA)       // 35328
#define SMEM_TOTAL (2 * STAGE)                // 70656

__device__ __align__(16) float  g_cur1[(size_t)M_TOTAL * N_HID];  // 82 MB scratch
__device__ __align__(16) __half g_w1h[NPB * N_IN];
__device__ __align__(16) __half g_w1l[NPB * N_IN];

// ---------------------------------------------------------------------------
__device__ __forceinline__ uint32_t smem_u32(const void* p) {
    uint32_t a;
    asm("{ .reg .u64 t; cvta.to.shared.u64 t, %1; cvt.u32.u64 %0, t; }" : "=r"(a) : "l"(p));
    return a;
}

#define LDSM4(r, addr)                                                          \
    asm volatile("ldmatrix.sync.aligned.m8n8.x4.shared.b16 {%0,%1,%2,%3}, [%4];" \
        : "=r"((r)[0]), "=r"((r)[1]), "=r"((r)[2]), "=r"((r)[3]) : "r"(addr))

#define LDSM2(r, addr)                                                          \
    asm volatile("ldmatrix.sync.aligned.m8n8.x2.shared.b16 {%0,%1}, [%2];"      \
        : "=r"((r)[0]), "=r"((r)[1]) : "r"(addr))

#define MMA16816(d, a, b0, b1)                                                  \
    asm volatile("mma.sync.aligned.m16n8k16.row.col.f32.f16.f16.f32 "           \
        "{%0,%1,%2,%3}, {%4,%5,%6,%7}, {%8,%9}, {%0,%1,%2,%3};"                 \
        : "+f"((d)[0]), "+f"((d)[1]), "+f"((d)[2]), "+f"((d)[3])                \
        : "r"((a)[0]), "r"((a)[1]), "r"((a)[2]), "r"((a)[3]), "r"(b0), "r"(b1))

// ---------------------------------------------------------------------------
// Kernel 0: split W1 into fp16 hi/lo (Dekker split), zero-padded to [112][784]
// ---------------------------------------------------------------------------
__global__ void w1_split(const float* __restrict__ W1) {
    int idx = blockIdx.x * 256 + threadIdx.x;
    if (idx >= NPB * N_IN) return;
    int n = idx / N_IN, k = idx % N_IN;
    float v = (n < N_HID) ? W1[n * N_IN + k] : 0.0f;
    __half h = __float2half_rn(v);
    g_w1h[idx] = h;
    g_w1l[idx] = __float2half_rn(v - __half2float(h));
}

// ---------------------------------------------------------------------------
// Kernel 1: cur1 = x @ W1^T + b1 via mma.sync fp16 3-product split.
// CTA: 512 thr, tile M=256 x N=112, K in 16-chunks, double-buffered smem.
// Warp grid 8(M) x 2(N): each warp 2 m16-tiles x 7 n8-tiles.
// ---------------------------------------------------------------------------
extern __shared__ char sm_buf[];

__global__ void __launch_bounds__(512) izh_gemm_hmma(
    const float* __restrict__ x, const float* __restrict__ b1)
{
    const int tid    = threadIdx.x;
    const int wid    = tid >> 5;
    const int lane   = tid & 31;
    const int warp_m = wid >> 1;        // 0..7
    const int warp_n = wid & 1;         // 0..1
    const int row0   = blockIdx.x * M_CTA;

    const uint32_t sb = smem_u32(sm_buf);

    // ldmatrix lane address offsets
    const uint32_t aLane = (uint32_t)((lane & 15) * SA + (lane >> 4) * 16);
    const uint32_t bLane = (uint32_t)((((lane & 7) + ((lane >> 4) << 3)) * SA) +
                                      (((lane >> 3) & 1) * 16));
    const uint32_t aWarp = (uint32_t)(warp_m * 32 * SA);
    const uint32_t bWarp = (uint32_t)(warp_n * 56 * SA);

    float acc[2][7][4];
    #pragma unroll
    for (int mt = 0; mt < 2; mt++)
        #pragma unroll
        for (int nt = 0; nt < 7; nt++)
            #pragma unroll
            for (int i = 0; i < 4; i++)
                acc[mt][nt][i] = 0.0f;

    float4 aReg[2];
    uint4  bReg = {};

    // ---- global load of one k-chunk into regs ----
    auto load_chunk = [&](int c) {
        const int k0 = c * 16;
        #pragma unroll
        for (int i = 0; i < 2; i++) {
            int id  = tid + i * 512;          // 0..1023
            int row = id >> 2, q = id & 3;
            aReg[i] = *(const float4*)(x + (size_t)(row0 + row) * N_IN + k0 + q * 4);
        }
        if (tid < 448) {
            int half = tid / 224, j = tid % 224;
            int row = j >> 1, part = j & 1;
            const __half* src = (half == 0 ? g_w1h : g_w1l) + row * N_IN + k0 + part * 8;
            bReg = *(const uint4*)src;
        }
    };

    // ---- split + store regs into smem stage s ----
    auto store_chunk = [&](int s) {
        char* st = sm_buf + s * STAGE;
        #pragma unroll
        for (int i = 0; i < 2; i++) {
            int id  = tid + i * 512;
            int row = id >> 2, q = id & 3;
            float4 v = aReg[i];
            __half2 h0 = __floats2half2_rn(v.x, v.y);
            __half2 h1 = __floats2half2_rn(v.z, v.w);
            float2 f0 = __half22float2(h0), f1 = __half22float2(h1);
            __half2 l0 = __floats2half2_rn(v.x - f0.x, v.y - f0.y);
            __half2 l1 = __floats2half2_rn(v.z - f1.x, v.w - f1.y);
            uint32_t off = (uint32_t)(row * SA + q * 8);
            *(uint2*)(st + A_HI_OFF + off) = make_uint2(*(uint32_t*)&h0, *(uint32_t*)&h1);
            *(uint2*)(st + A_LO_OFF + off) = make_uint2(*(uint32_t*)&l0, *(uint32_t*)&l1);
        }
        if (tid < 448) {
            int half = tid / 224, j = tid % 224;
            int row = j >> 1, part = j & 1;
            *(uint4*)(st + (half == 0 ? B_HI_OFF : B_LO_OFF) + row * SA + part * 16) = bReg;
        }
    };

    // ---- mma on smem stage s ----
    auto compute = [&](int s) {
        const uint32_t stage = sb + s * STAGE;
        uint32_t ahi[2][4], alo[2][4];
        #pragma unroll
        for (int mt = 0; mt < 2; mt++) {
            uint32_t addr = stage + A_HI_OFF + aWarp + mt * 16 * SA + aLane;
            LDSM4(ahi[mt], addr);
            LDSM4(alo[mt], addr + (A_LO_OFF - A_HI_OFF));
        }
        #pragma unroll
        for (int p = 0; p < 3; p++) {         // ntile pairs (0,1),(2,3),(4,5)
            uint32_t bh[4], bl[4];
            uint32_t addr = stage + B_HI_OFF + bWarp + p * 16 * SA + bLane;
            LDSM4(bh, addr);
            LDSM4(bl, addr + NPB * SA);
            #pragma unroll
            for (int mt = 0; mt < 2; mt++)
                #pragma unroll
                for (int q = 0; q < 2; q++) {
                    int nt = p * 2 + q;
                    MMA16816(acc[mt][nt], ahi[mt], bh[2 * q], bh[2 * q + 1]);
                    MMA16816(acc[mt][nt], ahi[mt], bl[2 * q], bl[2 * q + 1]);
                    MMA16816(acc[mt][nt], alo[mt], bh[2 * q], bh[2 * q + 1]);
                }
        }
        {                                      // ntile 6
            uint32_t bh[2], bl[2];
            uint32_t addr = stage + B_HI_OFF + bWarp + 48 * SA + bLane;
            LDSM2(bh, addr);
            LDSM2(bl, addr + NPB * SA);
            #pragma unroll
            for (int mt = 0; mt < 2; mt++) {
                MMA16816(acc[mt][6], ahi[mt], bh[0], bh[1]);
                MMA16816(acc[mt][6], ahi[mt], bl[0], bl[1]);
                MMA16816(acc[mt][6], alo[mt], bh[0], bh[1]);
            }
        }
    };

    // ---- pipeline ----
    load_chunk(0);
    store_chunk(0);
    for (int c = 0; c < NK; c++) {
        __syncthreads();
        if (c + 1 < NK) load_chunk(c + 1);
        compute(c & 1);
        if (c + 1 < NK) store_chunk((c + 1) & 1);
    }

    // ---- epilogue: add bias, store valid cols ----
    #pragma unroll
    for (int mt = 0; mt < 2; mt++) {
        int rbase = row0 + warp_m * 32 + mt * 16 + (lane >> 2);
        #pragma unroll
        for (int nt = 0; nt < 7; nt++) {
            int col = warp_n * 56 + nt * 8 + (lane & 3) * 2;
            if (col < N_HID) {
                float bb0 = __ldg(b1 + col), bb1 = __ldg(b1 + col + 1);
                float2 v0 = make_float2(acc[mt][nt][0] + bb0, acc[mt][nt][1] + bb1);
                float2 v1 = make_float2(acc[mt][nt][2] + bb0, acc[mt][nt][3] + bb1);
                *(float2*)(g_cur1 + (size_t)rbase * N_HID + col)       = v0;
                *(float2*)(g_cur1 + (size_t)(rbase + 8) * N_HID + col) = v1;
            }
        }
    }
}

// ---------------------------------------------------------------------------
// Kernel 2: sequential Izhikevich dynamics — one WARP per batch row.
// Lane l owns hidden neurons 4l..4l+3 (lanes 0..24). Layer-2 dot: spikes go
// to smem; lane l (<30) computes output (l%10) over an owned hidden chunk
// (uniform 9 x float4 loads, zero-padded overlap weights); 2 shfl_down reduce.
// ---------------------------------------------------------------------------
__global__ __launch_bounds__(32) void izh_loop3(
    const float* __restrict__ W2, const float* __restrict__ b2,
    float* __restrict__ out)
{
    const float A = 0.02f, Bp = 0.2f, Cp = -65.0f, Dp = 8.0f, THR = 0.03f;
    const int b = blockIdx.x;
    const int l = threadIdx.x;
    const int h0 = l * 4;
    const bool hv = (h0 < N_HID);      // lanes 0..24 hold hidden state

    __shared__ float spks[112];

    // layer-2 weight slice: lane l<30 -> output o=l%10, chunk ch=l/10.
    // chunk ch reads spks[32*ch .. 32*ch+35] (9 float4), owns
    // h in [ch==0 ? 0 : 32*ch+4, 32*ch+36); overlap weights zeroed.
    const int o  = l % N_OUT;
    const int ch = (l < 30) ? (l / 10) : 0;
    float wreg[36];
    #pragma unroll
    for (int j = 0; j < 36; j++) {
        int h = 32 * ch + j;
        bool own = (l < 30) && (h < N_HID) && (ch == 0 || j >= 4);
        wreg[j] = own ? W2[o * N_HID + h] : 0.0f;
    }
    const float bb = (l < N_OUT) ? b2[l] : 0.0f;

    float v1[4], u1[4];
    #pragma unroll
    for (int i = 0; i < 4; i++) { v1[i] = -70.0f; u1[i] = -15.0f; }
    float v2 = -70.0f, u2 = -15.0f;

    const float* curp = g_cur1 + (size_t)b * T_STEPS * N_HID;
    const size_t mem_off = (size_t)T_STEPS * BATCH * N_OUT;

    float4 I = hv ? *(const float4*)(curp + h0) : make_float4(0.f, 0.f, 0.f, 0.f);

    for (int t = 0; t < T_STEPS; t++) {
        float4 In = make_float4(0.f, 0.f, 0.f, 0.f);
        if (t + 1 < T_STEPS && hv)
            In = *(const float4*)(curp + (size_t)(t + 1) * N_HID + h0);

        // ---- layer-1 dynamics ----
        if (hv) {
            float Ia[4] = {I.x, I.y, I.z, I.w};
            float s[4];
            #pragma unroll
            for (int i = 0; i < 4; i++) {
                float vn = v1[i] + 0.04f * v1[i] * v1[i] + 5.0f * v1[i] + 140.0f - u1[i] + Ia[i];
                float un = u1[i] + A * (Bp * v1[i] - u1[i]);
                float sp = (vn >= THR) ? 1.0f : 0.0f;
                v1[i] = (sp > 0.0f) ? Cp : vn;
                u1[i] = (sp > 0.0f) ? (un + Dp) : un;
                s[i] = sp;
            }
            *(float4*)(spks + h0) = make_float4(s[0], s[1], s[2], s[3]);
        }
        __syncwarp();

        // ---- layer-2 partial dot (uniform across lanes; 4 accumulators) ----
        float a0 = 0.f, a1 = 0.f, a2 = 0.f, a3 = 0.f;
        const float4* sp4 = (const float4*)(spks + 32 * ch);
        #pragma unroll
        for (int j = 0; j < 9; j++) {
            float4 v = sp4[j];
            a0 += v.x * wreg[4 * j + 0];
            a1 += v.y * wreg[4 * j + 1];
            a2 += v.z * wreg[4 * j + 2];
            a3 += v.w * wreg[4 * j + 3];
        }
        float p = (a0 + a1) + (a2 + a3);
        float q1 = __shfl_down_sync(0xFFFFFFFFu, p, 10);
        float q2 = __shfl_down_sync(0xFFFFFFFFu, p, 20);

        if (l < N_OUT) {
            float c2 = p + q1 + q2 + bb;
            float vn = v2 + 0.04f * v2 * v2 + 5.0f * v2 + 140.0f - u2 + c2;
            float un = u2 + A * (Bp * v2 - u2);
            float sp = (vn >= THR) ? 1.0f : 0.0f;
            v2 = (sp > 0.0f) ? Cp : vn;
            u2 = (sp > 0.0f) ? (un + Dp) : un;
            size_t oo = ((size_t)t * BATCH + b) * N_OUT + l;
            out[oo]           = sp;
            out[mem_off + oo] = v2;
        }
        __syncwarp();   // spks reads done before next step overwrites
        I = In;
    }
}

// ---------------------------------------------------------------------------
extern "C" void kernel_launch(void* const* d_in, const int* in_sizes, int n_in,
                              void* d_out, int out_size)
{
    const float* x  = (const float*)d_in[0];
    const float* W1 = (const float*)d_in[1];
    const float* b1 = (const float*)d_in[2];
    const float* W2 = (const float*)d_in[3];
    const float* b2 = (const float*)d_in[4];
    float* out = (float*)d_out;
    (void)in_sizes; (void)n_in; (void)out_size;

    static bool attr_set = false;
    if (!attr_set) {
        cudaFuncSetAttribute(izh_gemm_hmma,
                             cudaFuncAttributeMaxDynamicSharedMemorySize, SMEM_TOTAL);
        attr_set = true;
    }

    w1_split<<<(NPB * N_IN + 255) / 256, 256>>>(W1);
    izh_gemm_hmma<<<M_TOTAL / M_CTA, 512, SMEM_TOTAL>>>(x, b1);
    izh_loop3<<<BATCH, 32>>>(W2, b2, out);
}

// round 5
// speedup vs baseline: 1.1163x; 1.1163x over previous
#include <cuda_runtime.h>
#include <cuda_fp16.h>
#include <cstdint>

#define T_STEPS 100
#define N_IN    784
#define N_HID   100
#define N_OUT   10
#define BATCH   2048
#define M_TOTAL (BATCH * T_STEPS)   // 204800
#define NPB     112                 // N padded to 14 * 8
#define NK      49                  // 784 / 16 k-chunks

// smem layout (per stage), 48-byte row pitch => conflict-free ldmatrix
#define SA        48
#define A_HI_OFF  0
#define A_LO_OFF  (128 * SA)                  // 6144
#define B_HI_OFF  (2 * 128 * SA)              // 12288
#define B_LO_OFF  (B_HI_OFF + NPB * SA)       // 17664
#define STAGE     (B_LO_OFF + NPB * SA)       // 23040
#define SMEM_TOTAL (2 * STAGE)                // 46080

__device__ __align__(16) float  g_cur1[(size_t)M_TOTAL * N_HID];  // 82 MB scratch
__device__ __align__(16) __half g_w1h[NPB * N_IN];
__device__ __align__(16) __half g_w1l[NPB * N_IN];

// ---------------------------------------------------------------------------
__device__ __forceinline__ uint32_t smem_u32(const void* p) {
    uint32_t a;
    asm("{ .reg .u64 t; cvta.to.shared.u64 t, %1; cvt.u32.u64 %0, t; }" : "=r"(a) : "l"(p));
    return a;
}

#define LDSM4(r, addr)                                                          \
    asm volatile("ldmatrix.sync.aligned.m8n8.x4.shared.b16 {%0,%1,%2,%3}, [%4];" \
        : "=r"((r)[0]), "=r"((r)[1]), "=r"((r)[2]), "=r"((r)[3]) : "r"(addr))

#define LDSM2(r, addr)                                                          \
    asm volatile("ldmatrix.sync.aligned.m8n8.x2.shared.b16 {%0,%1}, [%2];"      \
        : "=r"((r)[0]), "=r"((r)[1]) : "r"(addr))

#define MMA16816(d, a, b0, b1)                                                  \
    asm volatile("mma.sync.aligned.m16n8k16.row.col.f32.f16.f16.f32 "           \
        "{%0,%1,%2,%3}, {%4,%5,%6,%7}, {%8,%9}, {%0,%1,%2,%3};"                 \
        : "+f"((d)[0]), "+f"((d)[1]), "+f"((d)[2]), "+f"((d)[3])                \
        : "r"((a)[0]), "r"((a)[1]), "r"((a)[2]), "r"((a)[3]), "r"(b0), "r"(b1))

// ---------------------------------------------------------------------------
// Kernel 0: split W1 into fp16 hi/lo (Dekker split), zero-padded to [112][784]
// ---------------------------------------------------------------------------
__global__ void w1_split(const float* __restrict__ W1) {
    int idx = blockIdx.x * 256 + threadIdx.x;
    if (idx >= NPB * N_IN) return;
    int n = idx / N_IN, k = idx % N_IN;
    float v = (n < N_HID) ? W1[n * N_IN + k] : 0.0f;
    __half h = __float2half_rn(v);
    g_w1h[idx] = h;
    g_w1l[idx] = __float2half_rn(v - __half2float(h));
}

// ---------------------------------------------------------------------------
// Kernel 1: cur1 = x @ W1^T + b1 via mma.sync fp16 3-product split.
// CTA: 256 thr, tile M=128 x N=112, K in 16-chunks, double-buffered smem.
// Warp grid 4(M) x 2(N): each warp 2 m16-tiles x 7 n8-tiles. 2 CTAs/SM.
// ---------------------------------------------------------------------------
extern __shared__ char sm_buf[];

__global__ void __launch_bounds__(256, 2) izh_gemm_hmma(
    const float* __restrict__ x, const float* __restrict__ b1)
{
    const int tid    = threadIdx.x;
    const int wid    = tid >> 5;
    const int lane   = tid & 31;
    const int warp_m = wid >> 1;        // 0..3
    const int warp_n = wid & 1;         // 0..1
    const int row0   = blockIdx.x * 128;

    const uint32_t sb = smem_u32(sm_buf);

    // ldmatrix lane address offsets
    const uint32_t aLane = (uint32_t)((lane & 15) * SA + (lane >> 4) * 16);
    const uint32_t bLane = (uint32_t)((((lane & 7) + ((lane >> 4) << 3)) * SA) +
                                      (((lane >> 3) & 1) * 16));
    const uint32_t aWarp = (uint32_t)(warp_m * 32 * SA);
    const uint32_t bWarp = (uint32_t)(warp_n * 56 * SA);

    float acc[2][7][4];
    #pragma unroll
    for (int mt = 0; mt < 2; mt++)
        #pragma unroll
        for (int nt = 0; nt < 7; nt++)
            #pragma unroll
            for (int i = 0; i < 4; i++)
                acc[mt][nt][i] = 0.0f;

    float4 aReg[2];
    uint4  bReg[2] = {};

    // ---- global load of one k-chunk into regs ----
    auto load_chunk = [&](int c) {
        const int k0 = c * 16;
        #pragma unroll
        for (int i = 0; i < 2; i++) {
            int id  = tid + i * 256;          // 0..511
            int row = id >> 2, q = id & 3;
            aReg[i] = *(const float4*)(x + (size_t)(row0 + row) * N_IN + k0 + q * 4);
        }
        #pragma unroll
        for (int i = 0; i < 2; i++) {
            int id = tid + i * 256;
            if (id < 448) {
                int half = id / 224, j = id % 224;
                int row = j >> 1, part = j & 1;
                const __half* src = (half == 0 ? g_w1h : g_w1l) + row * N_IN + k0 + part * 8;
                bReg[i] = *(const uint4*)src;
            }
        }
    };

    // ---- split + store regs into smem stage s ----
    auto store_chunk = [&](int s) {
        char* st = sm_buf + s * STAGE;
        #pragma unroll
        for (int i = 0; i < 2; i++) {
            int id  = tid + i * 256;
            int row = id >> 2, q = id & 3;
            float4 v = aReg[i];
            __half2 h0 = __floats2half2_rn(v.x, v.y);
            __half2 h1 = __floats2half2_rn(v.z, v.w);
            float2 f0 = __half22float2(h0), f1 = __half22float2(h1);
            __half2 l0 = __floats2half2_rn(v.x - f0.x, v.y - f0.y);
            __half2 l1 = __floats2half2_rn(v.z - f1.x, v.w - f1.y);
            uint32_t off = (uint32_t)(row * SA + q * 8);
            *(uint2*)(st + A_HI_OFF + off) = make_uint2(*(uint32_t*)&h0, *(uint32_t*)&h1);
            *(uint2*)(st + A_LO_OFF + off) = make_uint2(*(uint32_t*)&l0, *(uint32_t*)&l1);
        }
        #pragma unroll
        for (int i = 0; i < 2; i++) {
            int id = tid + i * 256;
            if (id < 448) {
                int half = id / 224, j = id % 224;
                int row = j >> 1, part = j & 1;
                *(uint4*)(st + (half == 0 ? B_HI_OFF : B_LO_OFF) + row * SA + part * 16) = bReg[i];
            }
        }
    };

    // ---- mma on smem stage s ----
    auto compute = [&](int s) {
        const uint32_t stage = sb + s * STAGE;
        uint32_t ahi[2][4], alo[2][4];
        #pragma unroll
        for (int mt = 0; mt < 2; mt++) {
            uint32_t addr = stage + A_HI_OFF + aWarp + mt * 16 * SA + aLane;
            LDSM4(ahi[mt], addr);
            LDSM4(alo[mt], addr + (A_LO_OFF - A_HI_OFF));
        }
        #pragma unroll
        for (int p = 0; p < 3; p++) {         // ntile pairs (0,1),(2,3),(4,5)
            uint32_t bh[4], bl[4];
            uint32_t addr = stage + B_HI_OFF + bWarp + p * 16 * SA + bLane;
            LDSM4(bh, addr);
            LDSM4(bl, addr + NPB * SA);
            #pragma unroll
            for (int mt = 0; mt < 2; mt++)
                #pragma unroll
                for (int q = 0; q < 2; q++) {
                    int nt = p * 2 + q;
                    MMA16816(acc[mt][nt], ahi[mt], bh[2 * q], bh[2 * q + 1]);
                    MMA16816(acc[mt][nt], ahi[mt], bl[2 * q], bl[2 * q + 1]);
                    MMA16816(acc[mt][nt], alo[mt], bh[2 * q], bh[2 * q + 1]);
                }
        }
        {                                      // ntile 6
            uint32_t bh[2], bl[2];
            uint32_t addr = stage + B_HI_OFF + bWarp + 48 * SA + bLane;
            LDSM2(bh, addr);
            LDSM2(bl, addr + NPB * SA);
            #pragma unroll
            for (int mt = 0; mt < 2; mt++) {
                MMA16816(acc[mt][6], ahi[mt], bh[0], bh[1]);
                MMA16816(acc[mt][6], ahi[mt], bl[0], bl[1]);
                MMA16816(acc[mt][6], alo[mt], bh[0], bh[1]);
            }
        }
    };

    // ---- pipeline ----
    load_chunk(0);
    store_chunk(0);
    for (int c = 0; c < NK; c++) {
        __syncthreads();
        if (c + 1 < NK) load_chunk(c + 1);
        compute(c & 1);
        if (c + 1 < NK) store_chunk((c + 1) & 1);
    }

    // ---- epilogue: add bias, store valid cols ----
    #pragma unroll
    for (int mt = 0; mt < 2; mt++) {
        int rbase = row0 + warp_m * 32 + mt * 16 + (lane >> 2);
        #pragma unroll
        for (int nt = 0; nt < 7; nt++) {
            int col = warp_n * 56 + nt * 8 + (lane & 3) * 2;
            if (col < N_HID) {
                float bb0 = __ldg(b1 + col), bb1 = __ldg(b1 + col + 1);
                float2 v0 = make_float2(acc[mt][nt][0] + bb0, acc[mt][nt][1] + bb1);
                float2 v1 = make_float2(acc[mt][nt][2] + bb0, acc[mt][nt][3] + bb1);
                *(float2*)(g_cur1 + (size_t)rbase * N_HID + col)       = v0;
                *(float2*)(g_cur1 + (size_t)(rbase + 8) * N_HID + col) = v1;
            }
        }
    }
}

// ---------------------------------------------------------------------------
// Kernel 2: sequential Izhikevich dynamics — one WARP per batch row.
// Lane l owns hidden neurons 4l..4l+3 (lanes 0..24). Layer-2 dot: spikes go
// to smem; lane l (<30) computes output (l%10) over an owned hidden chunk
// (uniform 9 x float4 loads, zero-padded overlap weights); 2 shfl_down reduce.
// ---------------------------------------------------------------------------
__global__ __launch_bounds__(32) void izh_loop3(
    const float* __restrict__ W2, const float* __restrict__ b2,
    float* __restrict__ out)
{
    const float A = 0.02f, Bp = 0.2f, Cp = -65.0f, Dp = 8.0f, THR = 0.03f;
    const int b = blockIdx.x;
    const int l = threadIdx.x;
    const int h0 = l * 4;
    const bool hv = (h0 < N_HID);      // lanes 0..24 hold hidden state

    __shared__ float spks[112];

    // layer-2 weight slice: lane l<30 -> output o=l%10, chunk ch=l/10.
    const int o  = l % N_OUT;
    const int ch = (l < 30) ? (l / 10) : 0;
    float wreg[36];
    #pragma unroll
    for (int j = 0; j < 36; j++) {
        int h = 32 * ch + j;
        bool own = (l < 30) && (h < N_HID) && (ch == 0 || j >= 4);
        wreg[j] = own ? W2[o * N_HID + h] : 0.0f;
    }
    const float bb = (l < N_OUT) ? b2[l] : 0.0f;

    float v1[4], u1[4];
    #pragma unroll
    for (int i = 0; i < 4; i++) { v1[i] = -70.0f; u1[i] = -15.0f; }
    float v2 = -70.0f, u2 = -15.0f;

    const float* curp = g_cur1 + (size_t)b * T_STEPS * N_HID;
    const size_t mem_off = (size_t)T_STEPS * BATCH * N_OUT;

    float4 I = hv ? *(const float4*)(curp + h0) : make_float4(0.f, 0.f, 0.f, 0.f);

    for (int t = 0; t < T_STEPS; t++) {
        float4 In = make_float4(0.f, 0.f, 0.f, 0.f);
        if (t + 1 < T_STEPS && hv)
            In = *(const float4*)(curp + (size_t)(t + 1) * N_HID + h0);

        // ---- layer-1 dynamics ----
        if (hv) {
            float Ia[4] = {I.x, I.y, I.z, I.w};
            float s[4];
            #pragma unroll
            for (int i = 0; i < 4; i++) {
                float vn = v1[i] + 0.04f * v1[i] * v1[i] + 5.0f * v1[i] + 140.0f - u1[i] + Ia[i];
                float un = u1[i] + A * (Bp * v1[i] - u1[i]);
                float sp = (vn >= THR) ? 1.0f : 0.0f;
                v1[i] = (sp > 0.0f) ? Cp : vn;
                u1[i] = (sp > 0.0f) ? (un + Dp) : un;
                s[i] = sp;
            }
            *(float4*)(spks + h0) = make_float4(s[0], s[1], s[2], s[3]);
        }
        __syncwarp();

        // ---- layer-2 partial dot (uniform across lanes; 4 accumulators) ----
        float a0 = 0.f, a1 = 0.f, a2 = 0.f, a3 = 0.f;
        const float4* sp4 = (const float4*)(spks + 32 * ch);
        #pragma unroll
        for (int j = 0; j < 9; j++) {
            float4 v = sp4[j];
            a0 += v.x * wreg[4 * j + 0];
            a1 += v.y * wreg[4 * j + 1];
            a2 += v.z * wreg[4 * j + 2];
            a3 += v.w * wreg[4 * j + 3];
        }
        float p = (a0 + a1) + (a2 + a3);
        float q1 = __shfl_down_sync(0xFFFFFFFFu, p, 10);
        float q2 = __shfl_down_sync(0xFFFFFFFFu, p, 20);

        if (l < N_OUT) {
            float c2 = p + q1 + q2 + bb;
            float vn = v2 + 0.04f * v2 * v2 + 5.0f * v2 + 140.0f - u2 + c2;
            float un = u2 + A * (Bp * v2 - u2);
            float sp = (vn >= THR) ? 1.0f : 0.0f;
            v2 = (sp > 0.0f) ? Cp : vn;
            u2 = (sp > 0.0f) ? (un + Dp) : un;
            size_t oo = ((size_t)t * BATCH + b) * N_OUT + l;
            out[oo]           = sp;
            out[mem_off + oo] = v2;
        }
        __syncwarp();   // spks reads done before next step overwrites
        I = In;
    }
}

// ---------------------------------------------------------------------------
extern "C" void kernel_launch(void* const* d_in, const int* in_sizes, int n_in,
                              void* d_out, int out_size)
{
    const float* x  = (const float*)d_in[0];
    const float* W1 = (const float*)d_in[1];
    const float* b1 = (const float*)d_in[2];
    const float* W2 = (const float*)d_in[3];
    const float* b2 = (const float*)d_in[4];
    float* out = (float*)d_out;
    (void)in_sizes; (void)n_in; (void)out_size;

    w1_split<<<(NPB * N_IN + 255) / 256, 256>>>(W1);
    izh_gemm_hmma<<<M_TOTAL / 128, 256, SMEM_TOTAL>>>(x, b1);
    izh_loop3<<<BATCH, 32>>>(W2, b2, out);
}